// round 14
// baseline (speedup 1.0000x reference)
#include <cuda_runtime.h>
#include <cuda_fp16.h>
#include <cstdint>

// ---------------------------------------------------------------------------
// GINE encoder. GEMMs: fp16 mma.m16n8k16 + ldmatrix + cp.async double buffer.
// Node/edge hidden layers fused into GEMM A-producer (no x16 buffer).
// Layer MLP fused (GEMM1 -> t in SMEM -> GEMM2) with BK=64 (half the syncs).
// BN prep fused into bnapply. Scatter: flat per-(edge,chunk) RED.
// Feature dim padded 300 -> 320 (pad cols identically 0 everywhere).
// ---------------------------------------------------------------------------

#define D0      300
#define DP      320
#define NMAX    100000
#define EMAX    250000
#define GMAX    4096
#define NLAYER  5
#define BN_EPS  1e-5f

__device__ __half g_h16[(size_t)NMAX * DP];
__device__ __half g_e16[(size_t)EMAX * DP];
__device__ __half g_p16[(size_t)GMAX * DP];
__device__ __half g_w16[13 * DP * DP];
__device__ float  g_agg[(size_t)NMAX * DP];
__device__ float  g_pool[(size_t)GMAX * DP];
__device__ float  g_cnt[GMAX];
__device__ float  g_sum[NLAYER * DP];
__device__ float  g_sq [NLAYER * DP];

// ---------------------------------------------------------------------------
__device__ __forceinline__ uint2 pack4h(float a, float b, float c, float d) {
    __half2 h0 = __floats2half2_rn(a, b);
    __half2 h1 = __floats2half2_rn(c, d);
    uint2 u;
    u.x = *reinterpret_cast<uint32_t*>(&h0);
    u.y = *reinterpret_cast<uint32_t*>(&h1);
    return u;
}

__global__ void k_fill0(float4* p, int n4) {
    int i = blockIdx.x * blockDim.x + threadIdx.x;
    if (i < n4) p[i] = make_float4(0.f, 0.f, 0.f, 0.f);
}

// all 13 weight matrices -> fp16 [320 n][320 k], transposed + zero padded
__global__ void k_wcvt_all(const float* __restrict__ nW2, const float* __restrict__ eW2,
                           const float* __restrict__ mW1, const float* __restrict__ mW2,
                           const float* __restrict__ pW,  __half* __restrict__ out) {
    int idx = blockIdx.x * blockDim.x + threadIdx.x;
    if (idx >= 13 * DP * DP) return;
    int m = idx / (DP * DP);
    int r = idx - m * (DP * DP);
    int k = r / DP, n = r - (r / DP) * DP;
    const float* W;
    if (m == 0)       W = nW2;
    else if (m == 1)  W = eW2;
    else if (m < 7)   W = mW1 + (size_t)(m - 2) * D0 * D0;
    else if (m < 12)  W = mW2 + (size_t)(m - 7) * D0 * D0;
    else              W = pW;
    float v = (k < D0 && n < D0) ? W[k * D0 + n] : 0.f;
    out[(size_t)m * DP * DP + (size_t)n * DP + k] = __float2half_rn(v);
}

// flat scatter: one thread per (edge, 16B chunk); 38 chunks cover cols 0..303
__global__ void k_scatter(const int* __restrict__ src, const int* __restrict__ dst, int total) {
    int idx = blockIdx.x * blockDim.x + threadIdx.x;
    if (idx >= total) return;
    int e = idx / 38;
    int c = idx - e * 38;
    int s = src[e], d = dst[e];
    uint4 hu = *(const uint4*)(g_h16 + (size_t)s * DP + 8 * c);
    uint4 eu = *(const uint4*)(g_e16 + (size_t)e * DP + 8 * c);
    const __half2* h2 = (const __half2*)&hu;
    const __half2* e2 = (const __half2*)&eu;
    float v[8];
#pragma unroll
    for (int j = 0; j < 4; j++) {
        float2 fh = __half22float2(h2[j]);
        float2 fe = __half22float2(e2[j]);
        v[2 * j]     = fmaxf(fh.x + fe.x, 0.f);
        v[2 * j + 1] = fmaxf(fh.y + fe.y, 0.f);
    }
    float* ap = g_agg + (size_t)d * DP + 8 * c;
    asm volatile("red.global.add.v4.f32 [%0], {%1,%2,%3,%4};"
                 :: "l"(ap), "f"(v[0]), "f"(v[1]), "f"(v[2]), "f"(v[3]) : "memory");
    asm volatile("red.global.add.v4.f32 [%0], {%1,%2,%3,%4};"
                 :: "l"(ap + 4), "f"(v[4]), "f"(v[5]), "f"(v[6]), "f"(v[7]) : "memory");
}

// v = relu(bn(agg)); scale/shift computed per block from layer stats.
// LAST=false: h16 = v, agg = v. LAST=true: RED v into pool.
template <bool LAST>
__global__ void k_bnapply(const int* __restrict__ batch,
                          const float* __restrict__ gamma, const float* __restrict__ beta,
                          const float* __restrict__ sums, const float* __restrict__ sqs,
                          float invN, int N) {
    __shared__ float ssc[DP], ssh[DP];
    for (int j = threadIdx.x; j < DP; j += blockDim.x) {
        float mu  = sums[j] * invN;
        float var = sqs[j] * invN - mu * mu;
        float inv = rsqrtf(var + BN_EPS);
        float ga = (j < D0) ? gamma[j] : 0.f;
        float be = (j < D0) ? beta[j]  : 0.f;
        float sc = ga * inv;
        ssc[j] = sc;
        ssh[j] = be - mu * sc;
    }
    __syncthreads();
    int idx = blockIdx.x * blockDim.x + threadIdx.x;
    if (idx >= N * 80) return;
    int i = idx / 80;
    int c = (idx - i * 80) * 4;
    size_t off = (size_t)i * DP + c;
    float4 v = *(const float4*)(g_agg + off);
    v.x = fmaxf(fmaf(v.x, ssc[c + 0], ssh[c + 0]), 0.f);
    v.y = fmaxf(fmaf(v.y, ssc[c + 1], ssh[c + 1]), 0.f);
    v.z = fmaxf(fmaf(v.z, ssc[c + 2], ssh[c + 2]), 0.f);
    v.w = fmaxf(fmaf(v.w, ssc[c + 3], ssh[c + 3]), 0.f);
    if (!LAST) {
        *(uint2*)(g_h16 + off) = pack4h(v.x, v.y, v.z, v.w);
        *(float4*)(g_agg + off) = v;
    } else {
        int g = batch[i];
        float* pp = g_pool + (size_t)g * DP + c;
        asm volatile("red.global.add.v4.f32 [%0], {%1,%2,%3,%4};"
                     :: "l"(pp), "f"(v.x), "f"(v.y), "f"(v.z), "f"(v.w) : "memory");
    }
}

__global__ void k_count(const int* __restrict__ batch, int N) {
    int i = blockIdx.x * blockDim.x + threadIdx.x;
    if (i < N) atomicAdd(&g_cnt[batch[i]], 1.f);
}

// scale pooled rows, convert to fp16; zero pool + BN stats for next replay
__global__ void k_scalepool(int G) {
    int idx = blockIdx.x * blockDim.x + threadIdx.x;
    if (idx < NLAYER * DP) { g_sum[idx] = 0.f; g_sq[idx] = 0.f; }
    if (idx >= G * 80) return;
    int i = idx / 80;
    int c = (idx - i * 80) * 4;
    float s = 1.f / fmaxf(g_cnt[i], 1.f);
    float4 v = *(const float4*)(g_pool + (size_t)i * DP + c);
    *(uint2*)(g_p16 + (size_t)i * DP + c) = pack4h(v.x * s, v.y * s, v.z * s, v.w * s);
    *(float4*)(g_pool + (size_t)i * DP + c) = make_float4(0.f, 0.f, 0.f, 0.f);
}

// ---------------------------------------------------------------------------
// shared GEMM primitives
// ---------------------------------------------------------------------------
__device__ __forceinline__ void cp16(uint32_t dst, const void* src, bool pred) {
    int sz = pred ? 16 : 0;
    asm volatile("cp.async.ca.shared.global [%0], [%1], 16, %2;"
                 :: "r"(dst), "l"(src), "r"(sz));
}
__device__ __forceinline__ void ldsm4(uint32_t* r, uint32_t addr) {
    asm volatile("ldmatrix.sync.aligned.m8n8.x4.shared.b16 {%0,%1,%2,%3}, [%4];"
                 : "=r"(r[0]), "=r"(r[1]), "=r"(r[2]), "=r"(r[3]) : "r"(addr));
}
__device__ __forceinline__ void mma16(float* c, const uint32_t* a, const uint32_t* b) {
    asm volatile("mma.sync.aligned.m16n8k16.row.col.f32.f16.f16.f32 "
                 "{%0,%1,%2,%3}, {%4,%5,%6,%7}, {%8,%9}, {%0,%1,%2,%3};"
                 : "+f"(c[0]), "+f"(c[1]), "+f"(c[2]), "+f"(c[3])
                 : "r"(a[0]), "r"(a[1]), "r"(a[2]), "r"(a[3]), "r"(b[0]), "r"(b[1]));
}

// ---------------------------------------------------------------------------
// Standalone GEMM: block 128x160, 256 thr, 8 warps (4M x 2N), warp tile
// 32x80, 2 CTA/SM. (R13 proven config, BK=32.)
// ASRC: 0 = A fp16 via cp.async
//       2 = node hidden: A = relu([ch,fc] @ HW(2x300) + HB)
//       3 = edge hidden: A = relu(ea(3)  @ HW(3x300) + HB)
// EPI:  0 half out, 2 +emb gather (half C + fp32 Cb), 4 fp32 out stride 300.
// ---------------------------------------------------------------------------
#define BM 128
#define BN 160
#define BK 32
#define A_HALFS (BM * 40)                  // 5120
#define B_HALFS (BN * 40)                  // 6400
#define STG_HALFS (A_HALFS + B_HALFS)      // 11520
#define SMEM_BYTES (2 * STG_HALFS * 2)     // 46080 < 48K

template <int EPI, int ASRC>
__global__ __launch_bounds__(256, 2)
void k_gemm(const __half* __restrict__ A,
            const float* __restrict__ P0, const float* __restrict__ P1,
            const float* __restrict__ HW, const float* __restrict__ HB,
            const __half* __restrict__ Wt,
            const float* __restrict__ bias, void* __restrict__ Cv,
            float* __restrict__ Cb, int M,
            const int* __restrict__ zidx, const float* __restrict__ emb) {
    extern __shared__ __align__(16) char smraw[];
    uint32_t smbase = (uint32_t)__cvta_generic_to_shared(smraw);

    const int tid = threadIdx.x;
    const int lane = tid & 31;
    const int wid = tid >> 5;
    const int warp_m = wid & 3;
    const int warp_n = wid >> 2;
    const int grp = lane >> 2;
    const int tg  = lane & 3;
    const int row0 = blockIdx.y * BM;
    const int col0 = blockIdx.x * BN;

    float acc[2][10][4];
#pragma unroll
    for (int i = 0; i < 2; i++)
#pragma unroll
        for (int j = 0; j < 10; j++)
#pragma unroll
            for (int k = 0; k < 4; k++) acc[i][j][k] = 0.f;

    const int a_r = tid >> 1;
    const int a_c = tid & 1;

    const int grow = row0 + a_r;
    const bool rok = grow < M;
    float at0 = 0.f, at1 = 0.f, at2 = 0.f;
    if (ASRC == 2 && rok) { at0 = P0[grow]; at1 = P1[grow]; }
    if (ASRC == 3 && rok) {
        at0 = P0[3 * (size_t)grow + 0];
        at1 = P0[3 * (size_t)grow + 1];
        at2 = P0[3 * (size_t)grow + 2];
    }

    float ra[16];
    auto ldgH = [&](int k0) {
        int c0 = k0 + a_c * 16;
#pragma unroll
        for (int q = 0; q < 4; q++) {
            int cg = c0 + 4 * q;
            if (rok && cg < D0) {
                float4 w0 = *(const float4*)(HW + cg);
                float4 w1 = *(const float4*)(HW + D0 + cg);
                float4 bb = *(const float4*)(HB + cg);
                float4 w2 = make_float4(0.f, 0.f, 0.f, 0.f);
                if (ASRC == 3) w2 = *(const float4*)(HW + 2 * D0 + cg);
                ra[4 * q + 0] = fmaxf(fmaf(at0, w0.x, fmaf(at1, w1.x, fmaf(at2, w2.x, bb.x))), 0.f);
                ra[4 * q + 1] = fmaxf(fmaf(at0, w0.y, fmaf(at1, w1.y, fmaf(at2, w2.y, bb.y))), 0.f);
                ra[4 * q + 2] = fmaxf(fmaf(at0, w0.z, fmaf(at1, w1.z, fmaf(at2, w2.z, bb.z))), 0.f);
                ra[4 * q + 3] = fmaxf(fmaf(at0, w0.w, fmaf(at1, w1.w, fmaf(at2, w2.w, bb.w))), 0.f);
            } else {
                ra[4 * q + 0] = 0.f; ra[4 * q + 1] = 0.f;
                ra[4 * q + 2] = 0.f; ra[4 * q + 3] = 0.f;
            }
        }
    };
    auto stsH = [&](int stage) {
        char* p = smraw + stage * (STG_HALFS * 2) + (a_r * 40 + a_c * 16) * 2;
        uint2 p0 = pack4h(ra[0], ra[1], ra[2], ra[3]);
        uint2 p1 = pack4h(ra[4], ra[5], ra[6], ra[7]);
        *(uint4*)p = make_uint4(p0.x, p0.y, p1.x, p1.y);
        uint2 p2 = pack4h(ra[8], ra[9], ra[10], ra[11]);
        uint2 p3 = pack4h(ra[12], ra[13], ra[14], ra[15]);
        *(uint4*)(p + 16) = make_uint4(p2.x, p2.y, p3.x, p3.y);
    };
    auto loadA = [&](int stage, int k0) {
        uint32_t as = smbase + stage * (STG_HALFS * 2);
        const __half* s = A + (size_t)(rok ? grow : 0) * DP + k0 + a_c * 16;
        cp16(as + (a_r * 40 + a_c * 16) * 2, s, rok);
        cp16(as + (a_r * 40 + a_c * 16 + 8) * 2, s + 8, rok);
    };
    auto loadB = [&](int stage, int k0) {
        uint32_t bs = smbase + stage * (STG_HALFS * 2) + A_HALFS * 2;
#pragma unroll
        for (int it = 0; it < 3; it++) {
            int id = tid + it * 256;
            if (id < 640) {
                int r = id >> 2, c = id & 3;
                cp16(bs + (r * 40 + c * 8) * 2,
                     Wt + (size_t)(col0 + r) * DP + k0 + c * 8, true);
            }
        }
    };

    if (ASRC == 0) loadA(0, 0); else ldgH(0);
    loadB(0, 0);
    asm volatile("cp.async.commit_group;");

    const int NK = DP / BK;  // 10
    for (int it = 0; it < NK; it++) {
        if (ASRC != 0) stsH(it & 1);
        if (it + 1 < NK) {
            if (ASRC == 0) loadA((it + 1) & 1, (it + 1) * BK);
            else           ldgH((it + 1) * BK);
            loadB((it + 1) & 1, (it + 1) * BK);
            asm volatile("cp.async.commit_group;");
            asm volatile("cp.async.wait_group 1;");
        } else {
            asm volatile("cp.async.wait_group 0;");
        }
        __syncthreads();

        uint32_t as = smbase + (it & 1) * (STG_HALFS * 2);
        uint32_t bs = as + A_HALFS * 2;
        const int jj = lane >> 3, rr = lane & 7;
#pragma unroll
        for (int ks = 0; ks < 2; ks++) {
            uint32_t a[2][4];
#pragma unroll
            for (int mt = 0; mt < 2; mt++) {
                int m = warp_m * 32 + mt * 16 + (jj & 1) * 8 + rr;
                int kh = ks * 16 + (jj >> 1) * 8;
                ldsm4(a[mt], as + (m * 40 + kh) * 2);
            }
#pragma unroll
            for (int p = 0; p < 5; p++) {
                int n = warp_n * 80 + p * 16 + (jj >> 1) * 8 + rr;
                int kh = ks * 16 + (jj & 1) * 8;
                uint32_t r4[4];
                ldsm4(r4, bs + (n * 40 + kh) * 2);
                mma16(acc[0][2 * p],     a[0], r4);
                mma16(acc[0][2 * p + 1], a[0], r4 + 2);
                mma16(acc[1][2 * p],     a[1], r4);
                mma16(acc[1][2 * p + 1], a[1], r4 + 2);
            }
        }
        __syncthreads();
    }

#pragma unroll
    for (int nt = 0; nt < 10; nt++) {
        int cc = col0 + warp_n * 80 + nt * 8 + 2 * tg;
        float b0 = 0.f, b1 = 0.f;
        if (cc < D0) { b0 = bias[cc]; b1 = bias[cc + 1]; }
#pragma unroll
        for (int mt = 0; mt < 2; mt++) {
#pragma unroll
            for (int h = 0; h < 2; h++) {
                int r = row0 + warp_m * 32 + mt * 16 + grp + h * 8;
                if (r >= M) continue;
                float v0 = acc[mt][nt][h * 2 + 0] + b0;
                float v1 = acc[mt][nt][h * 2 + 1] + b1;
                if (EPI == 2) {
                    if (cc < D0) {
                        int zi = zidx[r];
                        v0 += emb[(size_t)zi * D0 + cc];
                        v1 += emb[(size_t)zi * D0 + cc + 1];
                    }
                }
                if (EPI == 0 || EPI == 2) {
                    __half2 hv = __floats2half2_rn(v0, v1);
                    *(uint32_t*)((__half*)Cv + (size_t)r * DP + cc) =
                        *reinterpret_cast<uint32_t*>(&hv);
                    if (EPI == 2)
                        *(float2*)(Cb + (size_t)r * DP + cc) = make_float2(v0, v1);
                } else {  // EPI 4
                    if (cc < D0)
                        *(float2*)((float*)Cv + (size_t)r * D0 + cc) = make_float2(v0, v1);
                }
            }
        }
    }
}

// ---------------------------------------------------------------------------
// Fused layer MLP with BK=64: agg_out = (relu(agg@W1+b1))@W2 + b2 + stats.
// Block 128 x 320, 512 thr, 16 warps (4M x 4N), warp tile 32x80.
// Row stride 72 halfs (144B): ldmatrix conflict-free (r*16 mod 128 distinct).
// NK = 5 per phase (half the syncs of BK=32).
// ---------------------------------------------------------------------------
#define MBK 64
#define KSTR 72
#define TSTR 328
#define T_HALFS (128 * TSTR)            // 41984
#define FA_HALFS (128 * KSTR)           // 9216
#define FB_HALFS (320 * KSTR)           // 23040
#define MLP_SMEM ((T_HALFS + 2 * FA_HALFS + 2 * FB_HALFS) * 2)  // 212992

__global__ __launch_bounds__(512, 1)
void k_mlp(const float* __restrict__ A, const __half* __restrict__ W1t,
           const float* __restrict__ b1v, const __half* __restrict__ W2t,
           const float* __restrict__ b2v, float* __restrict__ Cout,
           float* __restrict__ sumbuf, float* __restrict__ sqbuf, int M) {
    extern __shared__ __align__(16) char smraw[];
    uint32_t smbase = (uint32_t)__cvta_generic_to_shared(smraw);
    const uint32_t tb   = smbase;
    const uint32_t stA  = smbase + T_HALFS * 2;
    const uint32_t stB  = smbase + (T_HALFS + 2 * FA_HALFS) * 2;

    const int tid = threadIdx.x;
    const int lane = tid & 31;
    const int wid = tid >> 5;
    const int warp_m = wid & 3;
    const int warp_n = wid >> 2;
    const int grp = lane >> 2;
    const int tg  = lane & 3;
    const int row0 = blockIdx.x * 128;
    const int jj = lane >> 3, rr = lane & 7;

    float acc[2][10][4];
#pragma unroll
    for (int i = 0; i < 2; i++)
#pragma unroll
        for (int j = 0; j < 10; j++)
#pragma unroll
            for (int k = 0; k < 4; k++) acc[i][j][k] = 0.f;

    const int a_r = tid >> 2;          // 0..127
    const int a_c = tid & 3;           // 16-float chunk of 64

    float ra[16];
    auto ldgA = [&](int k0) {
        int grow = row0 + a_r;
        if (grow < M) {
            const float* s = A + (size_t)grow * DP + k0 + a_c * 16;
#pragma unroll
            for (int q = 0; q < 4; q++) {
                float4 u = *(const float4*)(s + 4 * q);
                ra[4 * q] = u.x; ra[4 * q + 1] = u.y;
                ra[4 * q + 2] = u.z; ra[4 * q + 3] = u.w;
            }
        } else {
#pragma unroll
            for (int j = 0; j < 16; j++) ra[j] = 0.f;
        }
    };
    auto stsA = [&](int stage) {
        char* p = smraw + (T_HALFS + stage * FA_HALFS + a_r * KSTR + a_c * 16) * 2;
        uint2 p0 = pack4h(ra[0], ra[1], ra[2], ra[3]);
        uint2 p1 = pack4h(ra[4], ra[5], ra[6], ra[7]);
        *(uint4*)p = make_uint4(p0.x, p0.y, p1.x, p1.y);
        uint2 p2 = pack4h(ra[8], ra[9], ra[10], ra[11]);
        uint2 p3 = pack4h(ra[12], ra[13], ra[14], ra[15]);
        *(uint4*)(p + 16) = make_uint4(p2.x, p2.y, p3.x, p3.y);
    };
    auto loadB = [&](const __half* W, int stage, int k0) {
        uint32_t bs = stB + stage * (FB_HALFS * 2);
#pragma unroll
        for (int it = 0; it < 5; it++) {
            int id = tid + it * 512;      // 2560 total = 320 rows x 8 chunks
            int r = id >> 3, c = id & 7;
            cp16(bs + (r * KSTR + c * 8) * 2,
                 W + (size_t)r * DP + k0 + c * 8, true);
        }
    };

    // ---------------- phase 1: t = relu(A @ W1 + b1) ----------------
    ldgA(0);
    loadB(W1t, 0, 0);
    asm volatile("cp.async.commit_group;");

    const int NK = DP / MBK;  // 5
    for (int it = 0; it < NK; it++) {
        stsA(it & 1);
        if (it + 1 < NK) {
            ldgA((it + 1) * MBK);
            loadB(W1t, (it + 1) & 1, (it + 1) * MBK);
            asm volatile("cp.async.commit_group;");
            asm volatile("cp.async.wait_group 1;");
        } else {
            asm volatile("cp.async.wait_group 0;");
        }
        __syncthreads();

        uint32_t as = stA + (it & 1) * (FA_HALFS * 2);
        uint32_t bs = stB + (it & 1) * (FB_HALFS * 2);
#pragma unroll
        for (int ks = 0; ks < 4; ks++) {
            uint32_t a[2][4];
#pragma unroll
            for (int mt = 0; mt < 2; mt++) {
                int m = warp_m * 32 + mt * 16 + (jj & 1) * 8 + rr;
                int kh = ks * 16 + (jj >> 1) * 8;
                ldsm4(a[mt], as + (m * KSTR + kh) * 2);
            }
#pragma unroll
            for (int p = 0; p < 5; p++) {
                int n = warp_n * 80 + p * 16 + (jj >> 1) * 8 + rr;
                int kh = ks * 16 + (jj & 1) * 8;
                uint32_t r4[4];
                ldsm4(r4, bs + (n * KSTR + kh) * 2);
                mma16(acc[0][2 * p],     a[0], r4);
                mma16(acc[0][2 * p + 1], a[0], r4 + 2);
                mma16(acc[1][2 * p],     a[1], r4);
                mma16(acc[1][2 * p + 1], a[1], r4 + 2);
            }
        }
        __syncthreads();
    }

    // prefetch W2 chunk 0 while epilogue runs
    loadB(W2t, 0, 0);
    asm volatile("cp.async.commit_group;");

    // epilogue 1: relu + bias -> t SMEM (fp16); reset acc
#pragma unroll
    for (int nt = 0; nt < 10; nt++) {
        int cc = warp_n * 80 + nt * 8 + 2 * tg;
        float b0 = 0.f, b1 = 0.f;
        if (cc < D0) { b0 = b1v[cc]; b1 = b1v[cc + 1]; }
#pragma unroll
        for (int mt = 0; mt < 2; mt++) {
#pragma unroll
            for (int h = 0; h < 2; h++) {
                int lr = warp_m * 32 + mt * 16 + grp + h * 8;
                float v0 = fmaxf(acc[mt][nt][h * 2 + 0] + b0, 0.f);
                float v1 = fmaxf(acc[mt][nt][h * 2 + 1] + b1, 0.f);
                __half2 hv = __floats2half2_rn(v0, v1);
                *(uint32_t*)(smraw + (lr * TSTR + cc) * 2) =
                    *reinterpret_cast<uint32_t*>(&hv);
                acc[mt][nt][h * 2 + 0] = 0.f;
                acc[mt][nt][h * 2 + 1] = 0.f;
            }
        }
    }
    __syncthreads();

    // ---------------- phase 2: out = t @ W2 + b2 (+ stats) ----------------
    for (int it = 0; it < NK; it++) {
        if (it + 1 < NK) {
            loadB(W2t, (it + 1) & 1, (it + 1) * MBK);
            asm volatile("cp.async.commit_group;");
            asm volatile("cp.async.wait_group 1;");
        } else {
            asm volatile("cp.async.wait_group 0;");
        }
        __syncthreads();

        int k0 = it * MBK;
        uint32_t bs = stB + (it & 1) * (FB_HALFS * 2);
#pragma unroll
        for (int ks = 0; ks < 4; ks++) {
            uint32_t a[2][4];
#pragma unroll
            for (int mt = 0; mt < 2; mt++) {
                int m = warp_m * 32 + mt * 16 + (jj & 1) * 8 + rr;
                int kh = k0 + ks * 16 + (jj >> 1) * 8;
                ldsm4(a[mt], tb + (m * TSTR + kh) * 2);
            }
#pragma unroll
            for (int p = 0; p < 5; p++) {
                int n = warp_n * 80 + p * 16 + (jj >> 1) * 8 + rr;
                int kh = ks * 16 + (jj & 1) * 8;
                uint32_t r4[4];
                ldsm4(r4, bs + (n * KSTR + kh) * 2);
                mma16(acc[0][2 * p],     a[0], r4);
                mma16(acc[0][2 * p + 1], a[0], r4 + 2);
                mma16(acc[1][2 * p],     a[1], r4);
                mma16(acc[1][2 * p + 1], a[1], r4 + 2);
            }
        }
        __syncthreads();
    }

    // epilogue 2: fp32 out + BN column stats
#pragma unroll
    for (int nt = 0; nt < 10; nt++) {
        int cc = warp_n * 80 + nt * 8 + 2 * tg;
        float b0 = 0.f, b1 = 0.f;
        if (cc < D0) { b0 = b2v[cc]; b1 = b2v[cc + 1]; }
        float s0 = 0.f, s1 = 0.f, q0 = 0.f, q1 = 0.f;
#pragma unroll
        for (int mt = 0; mt < 2; mt++) {
#pragma unroll
            for (int h = 0; h < 2; h++) {
                int r = row0 + warp_m * 32 + mt * 16 + grp + h * 8;
                if (r >= M) continue;
                float v0 = acc[mt][nt][h * 2 + 0] + b0;
                float v1 = acc[mt][nt][h * 2 + 1] + b1;
                s0 += v0; s1 += v1; q0 += v0 * v0; q1 += v1 * v1;
                *(float2*)(Cout + (size_t)r * DP + cc) = make_float2(v0, v1);
            }
        }
#pragma unroll
        for (int o = 4; o < 32; o <<= 1) {
            s0 += __shfl_xor_sync(0xffffffffu, s0, o);
            s1 += __shfl_xor_sync(0xffffffffu, s1, o);
            q0 += __shfl_xor_sync(0xffffffffu, q0, o);
            q1 += __shfl_xor_sync(0xffffffffu, q1, o);
        }
        if (grp == 0) {
            atomicAdd(&sumbuf[cc], s0);
            atomicAdd(&sumbuf[cc + 1], s1);
            atomicAdd(&sqbuf[cc], q0);
            atomicAdd(&sqbuf[cc + 1], q1);
        }
    }
}

// ---------------------------------------------------------------------------
extern "C" void kernel_launch(void* const* d_in, const int* in_sizes, int n_in,
                              void* d_out, int out_size) {
    const int*   z     = (const int*)d_in[0];
    const float* ch    = (const float*)d_in[1];
    const float* fc    = (const float*)d_in[2];
    const int*   ei    = (const int*)d_in[3];
    const float* ea    = (const float*)d_in[4];
    const int*   batch = (const int*)d_in[5];

    int o = (in_sizes[6] == 1) ? 7 : 6;
    const float* atom_emb = (const float*)d_in[o + 0];
    const float* nW1   = (const float*)d_in[o + 1];
    const float* nb1   = (const float*)d_in[o + 2];
    const float* nW2   = (const float*)d_in[o + 3];
    const float* nb2   = (const float*)d_in[o + 4];
    const float* eW1   = (const float*)d_in[o + 5];
    const float* eb1   = (const float*)d_in[o + 6];
    const float* eW2   = (const float*)d_in[o + 7];
    const float* eb2   = (const float*)d_in[o + 8];
    const float* mW1   = (const float*)d_in[o + 9];
    const float* mb1   = (const float*)d_in[o + 10];
    const float* mW2   = (const float*)d_in[o + 11];
    const float* mb2   = (const float*)d_in[o + 12];
    const float* gamma = (const float*)d_in[o + 13];
    const float* beta  = (const float*)d_in[o + 14];
    const float* pW    = (const float*)d_in[o + 15];
    const float* pb    = (const float*)d_in[o + 16];

    int N = in_sizes[0];
    int E = in_sizes[3] / 2;
    int G = out_size / D0;
    const int* src = ei;
    const int* dst = ei + E;

    __half *ph16, *pe16, *pp16, *pw16;
    float *pagg, *ppool, *pcnt, *psum, *psq;
    cudaGetSymbolAddress((void**)&ph16, g_h16);
    cudaGetSymbolAddress((void**)&pe16, g_e16);
    cudaGetSymbolAddress((void**)&pp16, g_p16);
    cudaGetSymbolAddress((void**)&pw16, g_w16);
    cudaGetSymbolAddress((void**)&pagg, g_agg);
    cudaGetSymbolAddress((void**)&ppool, g_pool);
    cudaGetSymbolAddress((void**)&pcnt, g_cnt);
    cudaGetSymbolAddress((void**)&psum, g_sum);
    cudaGetSymbolAddress((void**)&psq,  g_sq);

    cudaFuncSetAttribute(k_mlp, cudaFuncAttributeMaxDynamicSharedMemorySize, MLP_SMEM);

    const size_t WSZ = (size_t)DP * DP;
    int n4 = N * 80;
    int escat = E * 38;
    int g4 = G * 80;

    k_wcvt_all<<<(13 * DP * DP + 255) / 256, 256>>>(nW2, eW2, mW1, mW2, pW, pw16);

    k_fill0<<<(G / 4 + 255) / 256, 256>>>((float4*)pcnt, G / 4);
    k_count<<<(N + 255) / 256, 256>>>(batch, N);

    // node encoder (hidden fused): h16 = emb[z] + relu([ch,fc]@nW1+nb1)@nW2+nb2
    {
        dim3 grid(2, (N + BM - 1) / BM);
        k_gemm<2, 2><<<grid, 256, SMEM_BYTES>>>(nullptr, ch, fc, nW1, nb1,
                                                pw16 + 0 * WSZ, nb2, ph16, pagg,
                                                N, z, atom_emb);
    }
    // edge encoder (hidden fused): e16 = relu(ea@eW1+eb1)@eW2+eb2
    {
        dim3 grid(2, (E + BM - 1) / BM);
        k_gemm<0, 3><<<grid, 256, SMEM_BYTES>>>(nullptr, ea, nullptr, eW1, eb1,
                                                pw16 + 1 * WSZ, eb2, pe16, nullptr,
                                                E, nullptr, nullptr);
    }

    int mgrid = (N + 127) / 128;
    for (int l = 0; l < NLAYER; l++) {
        k_scatter<<<(escat + 255) / 256, 256>>>(src, dst, escat);
        k_mlp<<<mgrid, 512, MLP_SMEM>>>(pagg, pw16 + (2 + l) * WSZ, mb1 + (size_t)l * D0,
                                        pw16 + (7 + l) * WSZ, mb2 + (size_t)l * D0,
                                        pagg, psum + (size_t)l * DP, psq + (size_t)l * DP, N);
        if (l + 1 < NLAYER)
            k_bnapply<false><<<(n4 + 255) / 256, 256>>>(nullptr,
                gamma + (size_t)l * D0, beta + (size_t)l * D0,
                psum + (size_t)l * DP, psq + (size_t)l * DP, 1.f / (float)N, N);
        else
            k_bnapply<true><<<(n4 + 255) / 256, 256>>>(batch,
                gamma + (size_t)l * D0, beta + (size_t)l * D0,
                psum + (size_t)l * DP, psq + (size_t)l * DP, 1.f / (float)N, N);
    }

    k_scalepool<<<(g4 + 255) / 256, 256>>>(G);
    {
        dim3 grid(2, (G + BM - 1) / BM);
        k_gemm<4, 0><<<grid, 256, SMEM_BYTES>>>(pp16, nullptr, nullptr, nullptr, nullptr,
                                                pw16 + 12 * WSZ, pb, d_out, nullptr,
                                                G, nullptr, nullptr);
    }
}

// round 15
// speedup vs baseline: 1.0635x; 1.0635x over previous
#include <cuda_runtime.h>
#include <cuda_fp16.h>
#include <cstdint>

// ---------------------------------------------------------------------------
// GINE encoder. GEMMs: fp16 mma.m16n8k16 + ldmatrix + cp.async double buffer.
// Node/edge hidden layers fused into GEMM A-producer, hidden W staged in SMEM.
// Layer MLP fused (GEMM1 -> t in SMEM -> GEMM2), BK=32 (R13 proven config).
// BN prep fused into bnapply; stats/pool zeroing fused into scalepool.
// Feature dim padded 300 -> 320 (pad cols identically 0 everywhere).
// ---------------------------------------------------------------------------

#define D0      300
#define DP      320
#define NMAX    100000
#define EMAX    250000
#define GMAX    4096
#define NLAYER  5
#define BN_EPS  1e-5f

__device__ __half g_h16[(size_t)NMAX * DP];
__device__ __half g_e16[(size_t)EMAX * DP];
__device__ __half g_p16[(size_t)GMAX * DP];
__device__ __half g_w16[13 * DP * DP];
__device__ float  g_agg[(size_t)NMAX * DP];
__device__ float  g_pool[(size_t)GMAX * DP];
__device__ float  g_cnt[GMAX];
__device__ float  g_sum[NLAYER * DP];
__device__ float  g_sq [NLAYER * DP];

// ---------------------------------------------------------------------------
__device__ __forceinline__ uint2 pack4h(float a, float b, float c, float d) {
    __half2 h0 = __floats2half2_rn(a, b);
    __half2 h1 = __floats2half2_rn(c, d);
    uint2 u;
    u.x = *reinterpret_cast<uint32_t*>(&h0);
    u.y = *reinterpret_cast<uint32_t*>(&h1);
    return u;
}

__global__ void k_fill0(float4* p, int n4) {
    int i = blockIdx.x * blockDim.x + threadIdx.x;
    if (i < n4) p[i] = make_float4(0.f, 0.f, 0.f, 0.f);
}

// all 13 weight matrices -> fp16 [320 n][320 k], transposed + zero padded
__global__ void k_wcvt_all(const float* __restrict__ nW2, const float* __restrict__ eW2,
                           const float* __restrict__ mW1, const float* __restrict__ mW2,
                           const float* __restrict__ pW,  __half* __restrict__ out) {
    int idx = blockIdx.x * blockDim.x + threadIdx.x;
    if (idx >= 13 * DP * DP) return;
    int m = idx / (DP * DP);
    int r = idx - m * (DP * DP);
    int k = r / DP, n = r - (r / DP) * DP;
    const float* W;
    if (m == 0)       W = nW2;
    else if (m == 1)  W = eW2;
    else if (m < 7)   W = mW1 + (size_t)(m - 2) * D0 * D0;
    else if (m < 12)  W = mW2 + (size_t)(m - 7) * D0 * D0;
    else              W = pW;
    float v = (k < D0 && n < D0) ? W[k * D0 + n] : 0.f;
    out[(size_t)m * DP * DP + (size_t)n * DP + k] = __float2half_rn(v);
}

// flat scatter: one thread per (edge, 16B chunk); 38 chunks cover cols 0..303
__global__ void k_scatter(const int* __restrict__ src, const int* __restrict__ dst, int total) {
    int idx = blockIdx.x * blockDim.x + threadIdx.x;
    if (idx >= total) return;
    int e = idx / 38;
    int c = idx - e * 38;
    int s = src[e], d = dst[e];
    uint4 hu = *(const uint4*)(g_h16 + (size_t)s * DP + 8 * c);
    uint4 eu = *(const uint4*)(g_e16 + (size_t)e * DP + 8 * c);
    const __half2* h2 = (const __half2*)&hu;
    const __half2* e2 = (const __half2*)&eu;
    float v[8];
#pragma unroll
    for (int j = 0; j < 4; j++) {
        float2 fh = __half22float2(h2[j]);
        float2 fe = __half22float2(e2[j]);
        v[2 * j]     = fmaxf(fh.x + fe.x, 0.f);
        v[2 * j + 1] = fmaxf(fh.y + fe.y, 0.f);
    }
    float* ap = g_agg + (size_t)d * DP + 8 * c;
    asm volatile("red.global.add.v4.f32 [%0], {%1,%2,%3,%4};"
                 :: "l"(ap), "f"(v[0]), "f"(v[1]), "f"(v[2]), "f"(v[3]) : "memory");
    asm volatile("red.global.add.v4.f32 [%0], {%1,%2,%3,%4};"
                 :: "l"(ap + 4), "f"(v[4]), "f"(v[5]), "f"(v[6]), "f"(v[7]) : "memory");
}

// v = relu(bn(agg)); scale/shift computed per block from layer stats.
// LAST=false: h16 = v, agg = v. LAST=true: RED v into pool.
template <bool LAST>
__global__ void k_bnapply(const int* __restrict__ batch,
                          const float* __restrict__ gamma, const float* __restrict__ beta,
                          const float* __restrict__ sums, const float* __restrict__ sqs,
                          float invN, int N) {
    __shared__ float ssc[DP], ssh[DP];
    for (int j = threadIdx.x; j < DP; j += blockDim.x) {
        float mu  = sums[j] * invN;
        float var = sqs[j] * invN - mu * mu;
        float inv = rsqrtf(var + BN_EPS);
        float ga = (j < D0) ? gamma[j] : 0.f;
        float be = (j < D0) ? beta[j]  : 0.f;
        float sc = ga * inv;
        ssc[j] = sc;
        ssh[j] = be - mu * sc;
    }
    __syncthreads();
    int idx = blockIdx.x * blockDim.x + threadIdx.x;
    if (idx >= N * 80) return;
    int i = idx / 80;
    int c = (idx - i * 80) * 4;
    size_t off = (size_t)i * DP + c;
    float4 v = *(const float4*)(g_agg + off);
    v.x = fmaxf(fmaf(v.x, ssc[c + 0], ssh[c + 0]), 0.f);
    v.y = fmaxf(fmaf(v.y, ssc[c + 1], ssh[c + 1]), 0.f);
    v.z = fmaxf(fmaf(v.z, ssc[c + 2], ssh[c + 2]), 0.f);
    v.w = fmaxf(fmaf(v.w, ssc[c + 3], ssh[c + 3]), 0.f);
    if (!LAST) {
        *(uint2*)(g_h16 + off) = pack4h(v.x, v.y, v.z, v.w);
        *(float4*)(g_agg + off) = v;
    } else {
        int g = batch[i];
        float* pp = g_pool + (size_t)g * DP + c;
        asm volatile("red.global.add.v4.f32 [%0], {%1,%2,%3,%4};"
                     :: "l"(pp), "f"(v.x), "f"(v.y), "f"(v.z), "f"(v.w) : "memory");
    }
}

__global__ void k_count(const int* __restrict__ batch, int N) {
    int i = blockIdx.x * blockDim.x + threadIdx.x;
    if (i < N) atomicAdd(&g_cnt[batch[i]], 1.f);
}

// scale pooled rows, convert to fp16; zero pool + BN stats for next replay
__global__ void k_scalepool(int G) {
    int idx = blockIdx.x * blockDim.x + threadIdx.x;
    if (idx < NLAYER * DP) { g_sum[idx] = 0.f; g_sq[idx] = 0.f; }
    if (idx >= G * 80) return;
    int i = idx / 80;
    int c = (idx - i * 80) * 4;
    float s = 1.f / fmaxf(g_cnt[i], 1.f);
    float4 v = *(const float4*)(g_pool + (size_t)i * DP + c);
    *(uint2*)(g_p16 + (size_t)i * DP + c) = pack4h(v.x * s, v.y * s, v.z * s, v.w * s);
    *(float4*)(g_pool + (size_t)i * DP + c) = make_float4(0.f, 0.f, 0.f, 0.f);
}

// ---------------------------------------------------------------------------
// shared GEMM primitives
// ---------------------------------------------------------------------------
__device__ __forceinline__ void cp16(uint32_t dst, const void* src, bool pred) {
    int sz = pred ? 16 : 0;
    asm volatile("cp.async.ca.shared.global [%0], [%1], 16, %2;"
                 :: "r"(dst), "l"(src), "r"(sz));
}
__device__ __forceinline__ void ldsm4(uint32_t* r, uint32_t addr) {
    asm volatile("ldmatrix.sync.aligned.m8n8.x4.shared.b16 {%0,%1,%2,%3}, [%4];"
                 : "=r"(r[0]), "=r"(r[1]), "=r"(r[2]), "=r"(r[3]) : "r"(addr));
}
__device__ __forceinline__ void mma16(float* c, const uint32_t* a, const uint32_t* b) {
    asm volatile("mma.sync.aligned.m16n8k16.row.col.f32.f16.f16.f32 "
                 "{%0,%1,%2,%3}, {%4,%5,%6,%7}, {%8,%9}, {%0,%1,%2,%3};"
                 : "+f"(c[0]), "+f"(c[1]), "+f"(c[2]), "+f"(c[3])
                 : "r"(a[0]), "r"(a[1]), "r"(a[2]), "r"(a[3]), "r"(b[0]), "r"(b[1]));
}

// ---------------------------------------------------------------------------
// Standalone GEMM: block 128x160, 256 thr, 8 warps (4M x 2N), warp tile
// 32x80, 2 CTA/SM.
// ASRC: 0 = A fp16 via cp.async
//       2 = node hidden: A = relu([ch,fc] @ HW(2x300) + HB)  (W staged in SMEM)
//       3 = edge hidden: A = relu(ea(3)  @ HW(3x300) + HB)   (W staged in SMEM)
// EPI:  0 half out, 2 +emb gather (half C + fp32 Cb), 4 fp32 out stride 300.
// ---------------------------------------------------------------------------
#define BM 128
#define BN 160
#define BK 32
#define A_HALFS (BM * 40)                  // 5120
#define B_HALFS (BN * 40)                  // 6400
#define STG_HALFS (A_HALFS + B_HALFS)      // 11520
#define SMEM_BYTES (2 * STG_HALFS * 2)     // 46080
#define HW_BYTES (4 * DP * 4)              // 5120 (w0,w1,w2,b padded)
#define SMEM_BYTES_H (SMEM_BYTES + HW_BYTES)  // 51200

template <int EPI, int ASRC>
__global__ __launch_bounds__(256, 2)
void k_gemm(const __half* __restrict__ A,
            const float* __restrict__ P0, const float* __restrict__ P1,
            const float* __restrict__ HW, const float* __restrict__ HB,
            const __half* __restrict__ Wt,
            const float* __restrict__ bias, void* __restrict__ Cv,
            float* __restrict__ Cb, int M,
            const int* __restrict__ zidx, const float* __restrict__ emb) {
    extern __shared__ __align__(16) char smraw[];
    uint32_t smbase = (uint32_t)__cvta_generic_to_shared(smraw);
    float* hws = (float*)(smraw + SMEM_BYTES);   // staged hidden weights

    const int tid = threadIdx.x;
    const int lane = tid & 31;
    const int wid = tid >> 5;
    const int warp_m = wid & 3;
    const int warp_n = wid >> 2;
    const int grp = lane >> 2;
    const int tg  = lane & 3;
    const int row0 = blockIdx.y * BM;
    const int col0 = blockIdx.x * BN;

    // stage hidden weights (zero-padded) once per CTA
    if (ASRC != 0) {
        for (int j = tid; j < DP; j += 256) {
            bool in = j < D0;
            hws[j]          = in ? HW[j] : 0.f;
            hws[DP + j]     = in ? HW[D0 + j] : 0.f;
            hws[2 * DP + j] = (ASRC == 3 && in) ? HW[2 * D0 + j] : 0.f;
            hws[3 * DP + j] = in ? HB[j] : 0.f;
        }
        __syncthreads();
    }

    float acc[2][10][4];
#pragma unroll
    for (int i = 0; i < 2; i++)
#pragma unroll
        for (int j = 0; j < 10; j++)
#pragma unroll
            for (int k = 0; k < 4; k++) acc[i][j][k] = 0.f;

    const int a_r = tid >> 1;
    const int a_c = tid & 1;

    const int grow = row0 + a_r;
    const bool rok = grow < M;
    float at0 = 0.f, at1 = 0.f, at2 = 0.f;
    if (ASRC == 2 && rok) { at0 = P0[grow]; at1 = P1[grow]; }
    if (ASRC == 3 && rok) {
        at0 = P0[3 * (size_t)grow + 0];
        at1 = P0[3 * (size_t)grow + 1];
        at2 = P0[3 * (size_t)grow + 2];
    }

    float ra[16];
    auto ldgH = [&](int k0) {
        int c0 = k0 + a_c * 16;
#pragma unroll
        for (int q = 0; q < 4; q++) {
            int cg = c0 + 4 * q;
            float4 w0 = *(const float4*)(hws + cg);
            float4 w1 = *(const float4*)(hws + DP + cg);
            float4 bb = *(const float4*)(hws + 3 * DP + cg);
            float4 w2 = make_float4(0.f, 0.f, 0.f, 0.f);
            if (ASRC == 3) w2 = *(const float4*)(hws + 2 * DP + cg);
            ra[4 * q + 0] = fmaxf(fmaf(at0, w0.x, fmaf(at1, w1.x, fmaf(at2, w2.x, bb.x))), 0.f);
            ra[4 * q + 1] = fmaxf(fmaf(at0, w0.y, fmaf(at1, w1.y, fmaf(at2, w2.y, bb.y))), 0.f);
            ra[4 * q + 2] = fmaxf(fmaf(at0, w0.z, fmaf(at1, w1.z, fmaf(at2, w2.z, bb.z))), 0.f);
            ra[4 * q + 3] = fmaxf(fmaf(at0, w0.w, fmaf(at1, w1.w, fmaf(at2, w2.w, bb.w))), 0.f);
        }
        if (!rok) {
#pragma unroll
            for (int j = 0; j < 16; j++) ra[j] = 0.f;
        }
    };
    auto stsH = [&](int stage) {
        char* p = smraw + stage * (STG_HALFS * 2) + (a_r * 40 + a_c * 16) * 2;
        uint2 p0 = pack4h(ra[0], ra[1], ra[2], ra[3]);
        uint2 p1 = pack4h(ra[4], ra[5], ra[6], ra[7]);
        *(uint4*)p = make_uint4(p0.x, p0.y, p1.x, p1.y);
        uint2 p2 = pack4h(ra[8], ra[9], ra[10], ra[11]);
        uint2 p3 = pack4h(ra[12], ra[13], ra[14], ra[15]);
        *(uint4*)(p + 16) = make_uint4(p2.x, p2.y, p3.x, p3.y);
    };
    auto loadA = [&](int stage, int k0) {
        uint32_t as = smbase + stage * (STG_HALFS * 2);
        const __half* s = A + (size_t)(rok ? grow : 0) * DP + k0 + a_c * 16;
        cp16(as + (a_r * 40 + a_c * 16) * 2, s, rok);
        cp16(as + (a_r * 40 + a_c * 16 + 8) * 2, s + 8, rok);
    };
    auto loadB = [&](int stage, int k0) {
        uint32_t bs = smbase + stage * (STG_HALFS * 2) + A_HALFS * 2;
#pragma unroll
        for (int it = 0; it < 3; it++) {
            int id = tid + it * 256;
            if (id < 640) {
                int r = id >> 2, c = id & 3;
                cp16(bs + (r * 40 + c * 8) * 2,
                     Wt + (size_t)(col0 + r) * DP + k0 + c * 8, true);
            }
        }
    };

    if (ASRC == 0) loadA(0, 0); else ldgH(0);
    loadB(0, 0);
    asm volatile("cp.async.commit_group;");

    const int NK = DP / BK;  // 10
    for (int it = 0; it < NK; it++) {
        if (ASRC != 0) stsH(it & 1);
        if (it + 1 < NK) {
            if (ASRC == 0) loadA((it + 1) & 1, (it + 1) * BK);
            else           ldgH((it + 1) * BK);
            loadB((it + 1) & 1, (it + 1) * BK);
            asm volatile("cp.async.commit_group;");
            asm volatile("cp.async.wait_group 1;");
        } else {
            asm volatile("cp.async.wait_group 0;");
        }
        __syncthreads();

        uint32_t as = smbase + (it & 1) * (STG_HALFS * 2);
        uint32_t bs = as + A_HALFS * 2;
        const int jj = lane >> 3, rr = lane & 7;
#pragma unroll
        for (int ks = 0; ks < 2; ks++) {
            uint32_t a[2][4];
#pragma unroll
            for (int mt = 0; mt < 2; mt++) {
                int m = warp_m * 32 + mt * 16 + (jj & 1) * 8 + rr;
                int kh = ks * 16 + (jj >> 1) * 8;
                ldsm4(a[mt], as + (m * 40 + kh) * 2);
            }
#pragma unroll
            for (int p = 0; p < 5; p++) {
                int n = warp_n * 80 + p * 16 + (jj >> 1) * 8 + rr;
                int kh = ks * 16 + (jj & 1) * 8;
                uint32_t r4[4];
                ldsm4(r4, bs + (n * 40 + kh) * 2);
                mma16(acc[0][2 * p],     a[0], r4);
                mma16(acc[0][2 * p + 1], a[0], r4 + 2);
                mma16(acc[1][2 * p],     a[1], r4);
                mma16(acc[1][2 * p + 1], a[1], r4 + 2);
            }
        }
        __syncthreads();
    }

#pragma unroll
    for (int nt = 0; nt < 10; nt++) {
        int cc = col0 + warp_n * 80 + nt * 8 + 2 * tg;
        float b0 = 0.f, b1 = 0.f;
        if (cc < D0) { b0 = bias[cc]; b1 = bias[cc + 1]; }
#pragma unroll
        for (int mt = 0; mt < 2; mt++) {
#pragma unroll
            for (int h = 0; h < 2; h++) {
                int r = row0 + warp_m * 32 + mt * 16 + grp + h * 8;
                if (r >= M) continue;
                float v0 = acc[mt][nt][h * 2 + 0] + b0;
                float v1 = acc[mt][nt][h * 2 + 1] + b1;
                if (EPI == 2) {
                    if (cc < D0) {
                        int zi = zidx[r];
                        v0 += emb[(size_t)zi * D0 + cc];
                        v1 += emb[(size_t)zi * D0 + cc + 1];
                    }
                }
                if (EPI == 0 || EPI == 2) {
                    __half2 hv = __floats2half2_rn(v0, v1);
                    *(uint32_t*)((__half*)Cv + (size_t)r * DP + cc) =
                        *reinterpret_cast<uint32_t*>(&hv);
                    if (EPI == 2)
                        *(float2*)(Cb + (size_t)r * DP + cc) = make_float2(v0, v1);
                } else {  // EPI 4
                    if (cc < D0)
                        *(float2*)((float*)Cv + (size_t)r * D0 + cc) = make_float2(v0, v1);
                }
            }
        }
    }
}

// ---------------------------------------------------------------------------
// Fused layer MLP (R13 config, BK=32): agg_out = (relu(agg@W1+b1))@W2+b2 +stats.
// Block 128 x 320, 512 thr, 16 warps (4M x 4N), warp tile 32x80.
// ---------------------------------------------------------------------------
#define TSTR 328
#define T_HALFS (128 * TSTR)
#define FA_HALFS (128 * 40)
#define FB_HALFS (320 * 40)
#define MLP_SMEM ((T_HALFS + 2 * FA_HALFS + 2 * FB_HALFS) * 2)  // 155648

__global__ __launch_bounds__(512, 1)
void k_mlp(const float* __restrict__ A, const __half* __restrict__ W1t,
           const float* __restrict__ b1v, const __half* __restrict__ W2t,
           const float* __restrict__ b2v, float* __restrict__ Cout,
           float* __restrict__ sumbuf, float* __restrict__ sqbuf, int M) {
    extern __shared__ __align__(16) char smraw[];
    uint32_t smbase = (uint32_t)__cvta_generic_to_shared(smraw);
    const uint32_t tb   = smbase;
    const uint32_t stA  = smbase + T_HALFS * 2;
    const uint32_t stB  = smbase + (T_HALFS + 2 * FA_HALFS) * 2;

    const int tid = threadIdx.x;
    const int lane = tid & 31;
    const int wid = tid >> 5;
    const int warp_m = wid & 3;
    const int warp_n = wid >> 2;
    const int grp = lane >> 2;
    const int tg  = lane & 3;
    const int row0 = blockIdx.x * 128;
    const int jj = lane >> 3, rr = lane & 7;

    float acc[2][10][4];
#pragma unroll
    for (int i = 0; i < 2; i++)
#pragma unroll
        for (int j = 0; j < 10; j++)
#pragma unroll
            for (int k = 0; k < 4; k++) acc[i][j][k] = 0.f;

    const int a_r = tid >> 2;
    const int a_c = tid & 3;

    float ra[8];
    auto ldgA = [&](int k0) {
        int grow = row0 + a_r;
        if (grow < M) {
            const float* s = A + (size_t)grow * DP + k0 + a_c * 8;
            float4 u0 = *(const float4*)s;
            float4 u1 = *(const float4*)(s + 4);
            ra[0] = u0.x; ra[1] = u0.y; ra[2] = u0.z; ra[3] = u0.w;
            ra[4] = u1.x; ra[5] = u1.y; ra[6] = u1.z; ra[7] = u1.w;
        } else {
#pragma unroll
            for (int j = 0; j < 8; j++) ra[j] = 0.f;
        }
    };
    auto stsA = [&](int stage) {
        uint2 p0 = pack4h(ra[0], ra[1], ra[2], ra[3]);
        uint2 p1 = pack4h(ra[4], ra[5], ra[6], ra[7]);
        *(uint4*)(smraw + (T_HALFS + stage * FA_HALFS + a_r * 40 + a_c * 8) * 2) =
            make_uint4(p0.x, p0.y, p1.x, p1.y);
    };
    auto loadB = [&](const __half* W, int stage, int k0) {
        uint32_t bs = stB + stage * (FB_HALFS * 2);
#pragma unroll
        for (int it = 0; it < 3; it++) {
            int id = tid + it * 512;
            if (id < 1280) {
                int r = id >> 2, c = id & 3;
                cp16(bs + (r * 40 + c * 8) * 2,
                     W + (size_t)r * DP + k0 + c * 8, true);
            }
        }
    };

    // phase 1: t = relu(A @ W1 + b1)
    ldgA(0);
    loadB(W1t, 0, 0);
    asm volatile("cp.async.commit_group;");

    for (int it = 0; it < 10; it++) {
        stsA(it & 1);
        if (it + 1 < 10) {
            ldgA((it + 1) * BK);
            loadB(W1t, (it + 1) & 1, (it + 1) * BK);
            asm volatile("cp.async.commit_group;");
            asm volatile("cp.async.wait_group 1;");
        } else {
            asm volatile("cp.async.wait_group 0;");
        }
        __syncthreads();

        uint32_t as = stA + (it & 1) * (FA_HALFS * 2);
        uint32_t bs = stB + (it & 1) * (FB_HALFS * 2);
#pragma unroll
        for (int ks = 0; ks < 2; ks++) {
            uint32_t a[2][4];
#pragma unroll
            for (int mt = 0; mt < 2; mt++) {
                int m = warp_m * 32 + mt * 16 + (jj & 1) * 8 + rr;
                int kh = ks * 16 + (jj >> 1) * 8;
                ldsm4(a[mt], as + (m * 40 + kh) * 2);
            }
#pragma unroll
            for (int p = 0; p < 5; p++) {
                int n = warp_n * 80 + p * 16 + (jj >> 1) * 8 + rr;
                int kh = ks * 16 + (jj & 1) * 8;
                uint32_t r4[4];
                ldsm4(r4, bs + (n * 40 + kh) * 2);
                mma16(acc[0][2 * p],     a[0], r4);
                mma16(acc[0][2 * p + 1], a[0], r4 + 2);
                mma16(acc[1][2 * p],     a[1], r4);
                mma16(acc[1][2 * p + 1], a[1], r4 + 2);
            }
        }
        __syncthreads();
    }

    loadB(W2t, 0, 0);
    asm volatile("cp.async.commit_group;");

    // epilogue 1: relu + bias -> t SMEM (fp16); reset acc
#pragma unroll
    for (int nt = 0; nt < 10; nt++) {
        int cc = warp_n * 80 + nt * 8 + 2 * tg;
        float b0 = 0.f, b1 = 0.f;
        if (cc < D0) { b0 = b1v[cc]; b1 = b1v[cc + 1]; }
#pragma unroll
        for (int mt = 0; mt < 2; mt++) {
#pragma unroll
            for (int h = 0; h < 2; h++) {
                int lr = warp_m * 32 + mt * 16 + grp + h * 8;
                float v0 = fmaxf(acc[mt][nt][h * 2 + 0] + b0, 0.f);
                float v1 = fmaxf(acc[mt][nt][h * 2 + 1] + b1, 0.f);
                __half2 hv = __floats2half2_rn(v0, v1);
                *(uint32_t*)(smraw + (lr * TSTR + cc) * 2) =
                    *reinterpret_cast<uint32_t*>(&hv);
                acc[mt][nt][h * 2 + 0] = 0.f;
                acc[mt][nt][h * 2 + 1] = 0.f;
            }
        }
    }
    __syncthreads();

    // phase 2: out = t @ W2 + b2 (+ stats)
    for (int it = 0; it < 10; it++) {
        if (it + 1 < 10) {
            loadB(W2t, (it + 1) & 1, (it + 1) * BK);
            asm volatile("cp.async.commit_group;");
            asm volatile("cp.async.wait_group 1;");
        } else {
            asm volatile("cp.async.wait_group 0;");
        }
        __syncthreads();

        int k0 = it * BK;
        uint32_t bs = stB + (it & 1) * (FB_HALFS * 2);
#pragma unroll
        for (int ks = 0; ks < 2; ks++) {
            uint32_t a[2][4];
#pragma unroll
            for (int mt = 0; mt < 2; mt++) {
                int m = warp_m * 32 + mt * 16 + (jj & 1) * 8 + rr;
                int kh = k0 + ks * 16 + (jj >> 1) * 8;
                ldsm4(a[mt], tb + (m * TSTR + kh) * 2);
            }
#pragma unroll
            for (int p = 0; p < 5; p++) {
                int n = warp_n * 80 + p * 16 + (jj >> 1) * 8 + rr;
                int kh = ks * 16 + (jj & 1) * 8;
                uint32_t r4[4];
                ldsm4(r4, bs + (n * 40 + kh) * 2);
                mma16(acc[0][2 * p],     a[0], r4);
                mma16(acc[0][2 * p + 1], a[0], r4 + 2);
                mma16(acc[1][2 * p],     a[1], r4);
                mma16(acc[1][2 * p + 1], a[1], r4 + 2);
            }
        }
        __syncthreads();
    }

    // epilogue 2: fp32 out + BN column stats
#pragma unroll
    for (int nt = 0; nt < 10; nt++) {
        int cc = warp_n * 80 + nt * 8 + 2 * tg;
        float b0 = 0.f, b1 = 0.f;
        if (cc < D0) { b0 = b2v[cc]; b1 = b2v[cc + 1]; }
        float s0 = 0.f, s1 = 0.f, q0 = 0.f, q1 = 0.f;
#pragma unroll
        for (int mt = 0; mt < 2; mt++) {
#pragma unroll
            for (int h = 0; h < 2; h++) {
                int r = row0 + warp_m * 32 + mt * 16 + grp + h * 8;
                if (r >= M) continue;
                float v0 = acc[mt][nt][h * 2 + 0] + b0;
                float v1 = acc[mt][nt][h * 2 + 1] + b1;
                s0 += v0; s1 += v1; q0 += v0 * v0; q1 += v1 * v1;
                *(float2*)(Cout + (size_t)r * DP + cc) = make_float2(v0, v1);
            }
        }
#pragma unroll
        for (int o = 4; o < 32; o <<= 1) {
            s0 += __shfl_xor_sync(0xffffffffu, s0, o);
            s1 += __shfl_xor_sync(0xffffffffu, s1, o);
            q0 += __shfl_xor_sync(0xffffffffu, q0, o);
            q1 += __shfl_xor_sync(0xffffffffu, q1, o);
        }
        if (grp == 0) {
            atomicAdd(&sumbuf[cc], s0);
            atomicAdd(&sumbuf[cc + 1], s1);
            atomicAdd(&sqbuf[cc], q0);
            atomicAdd(&sqbuf[cc + 1], q1);
        }
    }
}

// ---------------------------------------------------------------------------
extern "C" void kernel_launch(void* const* d_in, const int* in_sizes, int n_in,
                              void* d_out, int out_size) {
    const int*   z     = (const int*)d_in[0];
    const float* ch    = (const float*)d_in[1];
    const float* fc    = (const float*)d_in[2];
    const int*   ei    = (const int*)d_in[3];
    const float* ea    = (const float*)d_in[4];
    const int*   batch = (const int*)d_in[5];

    int o = (in_sizes[6] == 1) ? 7 : 6;
    const float* atom_emb = (const float*)d_in[o + 0];
    const float* nW1   = (const float*)d_in[o + 1];
    const float* nb1   = (const float*)d_in[o + 2];
    const float* nW2   = (const float*)d_in[o + 3];
    const float* nb2   = (const float*)d_in[o + 4];
    const float* eW1   = (const float*)d_in[o + 5];
    const float* eb1   = (const float*)d_in[o + 6];
    const float* eW2   = (const float*)d_in[o + 7];
    const float* eb2   = (const float*)d_in[o + 8];
    const float* mW1   = (const float*)d_in[o + 9];
    const float* mb1   = (const float*)d_in[o + 10];
    const float* mW2   = (const float*)d_in[o + 11];
    const float* mb2   = (const float*)d_in[o + 12];
    const float* gamma = (const float*)d_in[o + 13];
    const float* beta  = (const float*)d_in[o + 14];
    const float* pW    = (const float*)d_in[o + 15];
    const float* pb    = (const float*)d_in[o + 16];

    int N = in_sizes[0];
    int E = in_sizes[3] / 2;
    int G = out_size / D0;
    const int* src = ei;
    const int* dst = ei + E;

    __half *ph16, *pe16, *pp16, *pw16;
    float *pagg, *ppool, *pcnt, *psum, *psq;
    cudaGetSymbolAddress((void**)&ph16, g_h16);
    cudaGetSymbolAddress((void**)&pe16, g_e16);
    cudaGetSymbolAddress((void**)&pp16, g_p16);
    cudaGetSymbolAddress((void**)&pw16, g_w16);
    cudaGetSymbolAddress((void**)&pagg, g_agg);
    cudaGetSymbolAddress((void**)&ppool, g_pool);
    cudaGetSymbolAddress((void**)&pcnt, g_cnt);
    cudaGetSymbolAddress((void**)&psum, g_sum);
    cudaGetSymbolAddress((void**)&psq,  g_sq);

    cudaFuncSetAttribute(k_mlp, cudaFuncAttributeMaxDynamicSharedMemorySize, MLP_SMEM);
    cudaFuncSetAttribute(k_gemm<2, 2>, cudaFuncAttributeMaxDynamicSharedMemorySize, SMEM_BYTES_H);
    cudaFuncSetAttribute(k_gemm<0, 3>, cudaFuncAttributeMaxDynamicSharedMemorySize, SMEM_BYTES_H);

    const size_t WSZ = (size_t)DP * DP;
    int n4 = N * 80;
    int escat = E * 38;
    int g4 = G * 80;

    k_wcvt_all<<<(13 * DP * DP + 255) / 256, 256>>>(nW2, eW2, mW1, mW2, pW, pw16);

    k_fill0<<<(G / 4 + 255) / 256, 256>>>((float4*)pcnt, G / 4);
    k_count<<<(N + 255) / 256, 256>>>(batch, N);

    // node encoder (hidden fused): h16 = emb[z] + relu([ch,fc]@nW1+nb1)@nW2+nb2
    {
        dim3 grid(2, (N + BM - 1) / BM);
        k_gemm<2, 2><<<grid, 256, SMEM_BYTES_H>>>(nullptr, ch, fc, nW1, nb1,
                                                  pw16 + 0 * WSZ, nb2, ph16, pagg,
                                                  N, z, atom_emb);
    }
    // edge encoder (hidden fused): e16 = relu(ea@eW1+eb1)@eW2+eb2
    {
        dim3 grid(2, (E + BM - 1) / BM);
        k_gemm<0, 3><<<grid, 256, SMEM_BYTES_H>>>(nullptr, ea, nullptr, eW1, eb1,
                                                  pw16 + 1 * WSZ, eb2, pe16, nullptr,
                                                  E, nullptr, nullptr);
    }

    int mgrid = (N + 127) / 128;
    for (int l = 0; l < NLAYER; l++) {
        k_scatter<<<(escat + 255) / 256, 256>>>(src, dst, escat);
        k_mlp<<<mgrid, 512, MLP_SMEM>>>(pagg, pw16 + (2 + l) * WSZ, mb1 + (size_t)l * D0,
                                        pw16 + (7 + l) * WSZ, mb2 + (size_t)l * D0,
                                        pagg, psum + (size_t)l * DP, psq + (size_t)l * DP, N);
        if (l + 1 < NLAYER)
            k_bnapply<false><<<(n4 + 255) / 256, 256>>>(nullptr,
                gamma + (size_t)l * D0, beta + (size_t)l * D0,
                psum + (size_t)l * DP, psq + (size_t)l * DP, 1.f / (float)N, N);
        else
            k_bnapply<true><<<(n4 + 255) / 256, 256>>>(batch,
                gamma + (size_t)l * D0, beta + (size_t)l * D0,
                psum + (size_t)l * DP, psq + (size_t)l * DP, 1.f / (float)N, N);
    }

    k_scalepool<<<(g4 + 255) / 256, 256>>>(G);
    {
        dim3 grid(2, (G + BM - 1) / BM);
        k_gemm<4, 0><<<grid, 256, SMEM_BYTES>>>(pp16, nullptr, nullptr, nullptr, nullptr,
                                                pw16 + 12 * WSZ, pb, d_out, nullptr,
                                                G, nullptr, nullptr);
    }
}